// round 1
// baseline (speedup 1.0000x reference)
#include <cuda_runtime.h>
#include <math.h>

// ---------------------------------------------------------------------------
// FCOS head: 5 levels, batch 2, C=256.
// Strategy: NHWC implicit-GEMM fp32 convs on CUDA cores (baseline),
// GroupNorm folded into per-(n,c) scale/shift, fused norm+ReLU,
// heads as small-N GEMMs with decode epilogue.
// ---------------------------------------------------------------------------

#define NLEV 5
#define TOTPIX 13343
#define OUTC 85
#define KDIM 2304            // 9 * 256
#define MAXFEAT (2*100*100*256)

// ------------------------- device scratch (no runtime alloc) ----------------
__device__ __align__(128) float g_P[MAXFEAT];   // transposed NHWC input of level
__device__ __align__(128) float g_A[MAXFEAT];   // normalized activations
__device__ __align__(128) float g_B[MAXFEAT];   // raw conv output
__device__ __align__(128) float g_Wt[8 * KDIM * 256]; // 8 tower layers, [K,256]
__device__ __align__(128) float g_Wc[KDIM * 80];      // cls head [K,80]
__device__ __align__(128) float g_Wr[KDIM * 5];       // reg(4)+iou(1) head [K,5]
__device__ float g_scale[512];  // per (n, c) affine from GN
__device__ float g_shift[512];

// ------------------------- weight transforms --------------------------------
// tower: w[l][co][ci][ky][kx] -> wt[(l*K + (t*256+ci))*256 + co]
__global__ void k_wtower(const float* __restrict__ w, float* __restrict__ wt,
                         int total) {
    int idx = blockIdx.x * 256 + threadIdx.x;
    if (idx >= total) return;
    int co = idx & 255;
    int r = idx >> 8;              // l*KDIM + k
    int k = r % KDIM;
    int l = r / KDIM;
    int t = k >> 8;
    int ci = k & 255;
    wt[idx] = w[(((long)l * 256 + co) * 256 + ci) * 9 + t];
}

__global__ void k_wc(const float* __restrict__ w, float* __restrict__ wc) {
    int idx = blockIdx.x * 256 + threadIdx.x;
    if (idx >= KDIM * 80) return;
    int co = idx % 80;
    int k = idx / 80;
    int t = k >> 8;
    int ci = k & 255;
    wc[idx] = w[((co * 256 + ci) * 9) + t];
}

__global__ void k_wr(const float* __restrict__ wreg, const float* __restrict__ wiou,
                     float* __restrict__ wr) {
    int idx = blockIdx.x * 256 + threadIdx.x;
    if (idx >= KDIM * 5) return;
    int j = idx % 5;
    int k = idx / 5;
    int t = k >> 8;
    int ci = k & 255;
    wr[idx] = (j < 4) ? wreg[((j * 256 + ci) * 9) + t]
                      : wiou[(ci * 9) + t];
}

// ------------------------- NCHW -> NHWC transpose ----------------------------
// in: [2,256,HW]  out: [2,HW,256]
__global__ void k_transpose(const float* __restrict__ in, float* __restrict__ out,
                            int HW) {
    __shared__ float tile[32][33];
    int n = blockIdx.z;
    int c0 = blockIdx.y * 32;
    int s0 = blockIdx.x * 32;
    int tx = threadIdx.x, ty = threadIdx.y;
    #pragma unroll
    for (int i = ty; i < 32; i += 8) {
        int s = s0 + tx;
        tile[i][tx] = (s < HW) ? in[((long)n * 256 + c0 + i) * HW + s] : 0.f;
    }
    __syncthreads();
    #pragma unroll
    for (int i = ty; i < 32; i += 8) {
        int s = s0 + i;
        if (s < HW) out[((long)n * HW + s) * 256 + c0 + tx] = tile[tx][i];
    }
}

// ------------------------- conv implicit GEMM (BN=128) -----------------------
// X: NHWC [2,H,W,256].  Wt: [KDIM,256].  Y[m, co] = bias[co] + sum_k A[m,k]W[k,co]
// K ordered tap-major (tap = ky*3+kx), ci-minor.
#define BM 128
#define BK 16

__global__ __launch_bounds__(256) void k_conv(
    const float* __restrict__ X, const float* __restrict__ Wt,
    const float* __restrict__ bias, float* __restrict__ Y,
    int H, int Wd, int HW, int M) {
    __shared__ float As[BK][BM + 4];
    __shared__ float Bs[BK][128];

    int tid = threadIdx.x;
    int bm = blockIdx.x, bn = blockIdx.y;
    int tm = tid >> 4;          // 0..15, 8 rows each
    int tn = tid & 15;          // 0..15, 8 cols each

    // A loader: row = tid&127, half = tid>>7 (8 ci each)
    int ar = tid & 127;
    int ah = tid >> 7;
    int am = bm * BM + ar;
    int an = 0, ay = 0, ax = 0;
    bool arv = (am < M);
    if (arv) { an = am / HW; int p = am - an * HW; ay = p / Wd; ax = p - ay * Wd; }
    int abase = an * HW;
    int kc = ah * 8;

    // B loader
    int bk = tid >> 4;
    int bc = (tid & 15) * 8;

    float acc[8][8];
    #pragma unroll
    for (int i = 0; i < 8; i++)
        #pragma unroll
        for (int j = 0; j < 8; j++) acc[i][j] = 0.f;

    for (int kk = 0; kk < 144; kk++) {
        int tap = kk >> 4;
        int dy = tap / 3 - 1;
        int dx = tap - (tap / 3) * 3 - 1;
        int ci0 = (kk & 15) << 4;

        float4 v0 = make_float4(0.f, 0.f, 0.f, 0.f);
        float4 v1 = make_float4(0.f, 0.f, 0.f, 0.f);
        int yy = ay + dy, xx = ax + dx;
        if (arv && (unsigned)yy < (unsigned)H && (unsigned)xx < (unsigned)Wd) {
            const float4* src = (const float4*)(X + (((long)(abase + yy * Wd + xx)) << 8) + ci0 + kc);
            v0 = src[0]; v1 = src[1];
        }
        const float4* bsrc = (const float4*)(Wt + ((long)(kk * 16 + bk)) * 256 + (bn << 7) + bc);
        float4 w0 = bsrc[0], w1 = bsrc[1];

        __syncthreads();
        As[kc + 0][ar] = v0.x; As[kc + 1][ar] = v0.y;
        As[kc + 2][ar] = v0.z; As[kc + 3][ar] = v0.w;
        As[kc + 4][ar] = v1.x; As[kc + 5][ar] = v1.y;
        As[kc + 6][ar] = v1.z; As[kc + 7][ar] = v1.w;
        *(float4*)&Bs[bk][bc] = w0;
        *(float4*)&Bs[bk][bc + 4] = w1;
        __syncthreads();

        #pragma unroll
        for (int k = 0; k < BK; k++) {
            float4 a0 = *(const float4*)&As[k][tm * 8];
            float4 a1 = *(const float4*)&As[k][tm * 8 + 4];
            float4 b0 = *(const float4*)&Bs[k][tn * 8];
            float4 b1 = *(const float4*)&Bs[k][tn * 8 + 4];
            float a[8] = {a0.x, a0.y, a0.z, a0.w, a1.x, a1.y, a1.z, a1.w};
            float b[8] = {b0.x, b0.y, b0.z, b0.w, b1.x, b1.y, b1.z, b1.w};
            #pragma unroll
            for (int i = 0; i < 8; i++)
                #pragma unroll
                for (int j = 0; j < 8; j++)
                    acc[i][j] = fmaf(a[i], b[j], acc[i][j]);
        }
    }

    float bb[8];
    #pragma unroll
    for (int j = 0; j < 8; j++) bb[j] = bias[(bn << 7) + tn * 8 + j];
    #pragma unroll
    for (int i = 0; i < 8; i++) {
        int m = bm * BM + tm * 8 + i;
        if (m < M) {
            float4 o0, o1;
            o0.x = acc[i][0] + bb[0]; o0.y = acc[i][1] + bb[1];
            o0.z = acc[i][2] + bb[2]; o0.w = acc[i][3] + bb[3];
            o1.x = acc[i][4] + bb[4]; o1.y = acc[i][5] + bb[5];
            o1.z = acc[i][6] + bb[6]; o1.w = acc[i][7] + bb[7];
            float4* dst = (float4*)(Y + (((long)m) << 8) + (bn << 7) + tn * 8);
            dst[0] = o0; dst[1] = o1;
        }
    }
}

// ------------------------- GroupNorm stats -> per-(n,c) affine ---------------
__global__ void k_stats(const float* __restrict__ Y,
                        const float* __restrict__ gamma, const float* __restrict__ beta,
                        float* __restrict__ scale, float* __restrict__ shift, int HW) {
    int n = blockIdx.x >> 5;
    int g = blockIdx.x & 31;
    int tid = threadIdx.x;
    const float* base = Y + ((long)n * HW) * 256 + g * 8;
    float s = 0.f, ss = 0.f;
    for (int p = tid; p < HW; p += 256) {
        const float4* q = (const float4*)(base + ((long)p) * 256);
        float4 a = q[0], b = q[1];
        s += a.x + a.y + a.z + a.w + b.x + b.y + b.z + b.w;
        ss += a.x * a.x + a.y * a.y + a.z * a.z + a.w * a.w
            + b.x * b.x + b.y * b.y + b.z * b.z + b.w * b.w;
    }
    #pragma unroll
    for (int o = 16; o; o >>= 1) {
        s += __shfl_xor_sync(0xffffffffu, s, o);
        ss += __shfl_xor_sync(0xffffffffu, ss, o);
    }
    __shared__ float rs[8], rss[8];
    if ((tid & 31) == 0) { rs[tid >> 5] = s; rss[tid >> 5] = ss; }
    __syncthreads();
    if (tid == 0) {
        float S = 0.f, SS = 0.f;
        #pragma unroll
        for (int i = 0; i < 8; i++) { S += rs[i]; SS += rss[i]; }
        float cnt = (float)HW * 8.f;
        float mean = S / cnt;
        float var = SS / cnt - mean * mean;
        float rstd = rsqrtf(var + 1e-5f);
        #pragma unroll
        for (int c = 0; c < 8; c++) {
            int ch = g * 8 + c;
            float sc = rstd * gamma[ch];
            scale[n * 256 + ch] = sc;
            shift[n * 256 + ch] = beta[ch] - mean * sc;
        }
    }
}

// ------------------------- norm + ReLU ---------------------------------------
__global__ void k_normrelu(const float* __restrict__ Y,
                           const float* __restrict__ scale, const float* __restrict__ shift,
                           float* __restrict__ X, int HW, int total4) {
    int idx = blockIdx.x * 256 + threadIdx.x;
    if (idx >= total4) return;
    int per = HW * 64;
    int n = idx / per;
    int c = (idx & 63) * 4;
    float4 v = ((const float4*)Y)[idx];
    float4 sc = *(const float4*)(scale + n * 256 + c);
    float4 sf = *(const float4*)(shift + n * 256 + c);
    float4 o;
    o.x = fmaxf(fmaf(v.x, sc.x, sf.x), 0.f);
    o.y = fmaxf(fmaf(v.y, sc.y, sf.y), 0.f);
    o.z = fmaxf(fmaf(v.z, sc.z, sf.z), 0.f);
    o.w = fmaxf(fmaf(v.w, sc.w, sf.w), 0.f);
    ((float4*)X)[idx] = o;
}

// ------------------------- cls head (N=80) -----------------------------------
__global__ __launch_bounds__(256) void k_clshead(
    const float* __restrict__ X, const float* __restrict__ Wc,
    const float* __restrict__ hb,
    int H, int Wd, int HW, int M, int pixbase, float* __restrict__ out) {
    __shared__ float As[BK][BM + 4];
    __shared__ float Bs[BK][80];

    int tid = threadIdx.x;
    int bm = blockIdx.x;
    int tm = tid >> 4;          // 8 rows
    int tn = tid & 15;          // 5 cols

    int ar = tid & 127;
    int ah = tid >> 7;
    int am = bm * BM + ar;
    int an = 0, ay = 0, ax = 0;
    bool arv = (am < M);
    if (arv) { an = am / HW; int p = am - an * HW; ay = p / Wd; ax = p - ay * Wd; }
    int abase = an * HW;
    int kc = ah * 8;

    int lk = tid >> 4;          // B loader: k row
    int lc = (tid & 15) * 5;    // 5 cols each

    float acc[8][5];
    #pragma unroll
    for (int i = 0; i < 8; i++)
        #pragma unroll
        for (int j = 0; j < 5; j++) acc[i][j] = 0.f;

    for (int kk = 0; kk < 144; kk++) {
        int tap = kk >> 4;
        int dy = tap / 3 - 1;
        int dx = tap - (tap / 3) * 3 - 1;
        int ci0 = (kk & 15) << 4;

        float4 v0 = make_float4(0.f, 0.f, 0.f, 0.f);
        float4 v1 = make_float4(0.f, 0.f, 0.f, 0.f);
        int yy = ay + dy, xx = ax + dx;
        if (arv && (unsigned)yy < (unsigned)H && (unsigned)xx < (unsigned)Wd) {
            const float4* src = (const float4*)(X + (((long)(abase + yy * Wd + xx)) << 8) + ci0 + kc);
            v0 = src[0]; v1 = src[1];
        }
        float wv[5];
        #pragma unroll
        for (int j = 0; j < 5; j++)
            wv[j] = Wc[((long)(kk * 16 + lk)) * 80 + lc + j];

        __syncthreads();
        As[kc + 0][ar] = v0.x; As[kc + 1][ar] = v0.y;
        As[kc + 2][ar] = v0.z; As[kc + 3][ar] = v0.w;
        As[kc + 4][ar] = v1.x; As[kc + 5][ar] = v1.y;
        As[kc + 6][ar] = v1.z; As[kc + 7][ar] = v1.w;
        #pragma unroll
        for (int j = 0; j < 5; j++) Bs[lk][lc + j] = wv[j];
        __syncthreads();

        #pragma unroll
        for (int k = 0; k < BK; k++) {
            float4 a0 = *(const float4*)&As[k][tm * 8];
            float4 a1 = *(const float4*)&As[k][tm * 8 + 4];
            float a[8] = {a0.x, a0.y, a0.z, a0.w, a1.x, a1.y, a1.z, a1.w};
            float b[5];
            #pragma unroll
            for (int j = 0; j < 5; j++) b[j] = Bs[k][tn * 5 + j];
            #pragma unroll
            for (int i = 0; i < 8; i++)
                #pragma unroll
                for (int j = 0; j < 5; j++)
                    acc[i][j] = fmaf(a[i], b[j], acc[i][j]);
        }
    }

    float bb[5];
    #pragma unroll
    for (int j = 0; j < 5; j++) bb[j] = hb[tn * 5 + j];
    #pragma unroll
    for (int i = 0; i < 8; i++) {
        int m = bm * BM + tm * 8 + i;
        if (m < M) {
            int n = m / HW;
            int p = m - n * HW;
            long row = (long)n * TOTPIX + pixbase + p;
            float* o = out + row * OUTC + 5 + tn * 5;
            #pragma unroll
            for (int j = 0; j < 5; j++) o[j] = acc[i][j] + bb[j];
        }
    }
}

// ------------------------- reg+iou head (N=5) + decode -----------------------
__global__ __launch_bounds__(256) void k_reghead(
    const float* __restrict__ X, const float* __restrict__ Wr,
    const float* __restrict__ rb, const float* __restrict__ ib,
    const float* __restrict__ scales, int level,
    int H, int Wd, int HW, int M, int pixbase, float strd,
    float* __restrict__ out) {
    __shared__ float As[16][260];
    __shared__ float Bs[16][5];

    int tid = threadIdx.x;
    int m = blockIdx.x * 256 + tid;
    bool rv = (m < M);
    int n = 0, y = 0, x = 0;
    if (rv) { n = m / HW; int p = m - n * HW; y = p / Wd; x = p - y * Wd; }
    int abase = n * HW;

    float acc[5] = {0.f, 0.f, 0.f, 0.f, 0.f};

    for (int kk = 0; kk < 144; kk++) {
        int tap = kk >> 4;
        int dy = tap / 3 - 1;
        int dx = tap - (tap / 3) * 3 - 1;
        int ci0 = (kk & 15) << 4;

        float4 v[4];
        #pragma unroll
        for (int q = 0; q < 4; q++) v[q] = make_float4(0.f, 0.f, 0.f, 0.f);
        int yy = y + dy, xx = x + dx;
        if (rv && (unsigned)yy < (unsigned)H && (unsigned)xx < (unsigned)Wd) {
            const float4* src = (const float4*)(X + (((long)(abase + yy * Wd + xx)) << 8) + ci0);
            v[0] = src[0]; v[1] = src[1]; v[2] = src[2]; v[3] = src[3];
        }
        __syncthreads();
        #pragma unroll
        for (int q = 0; q < 4; q++) {
            As[q * 4 + 0][tid] = v[q].x;
            As[q * 4 + 1][tid] = v[q].y;
            As[q * 4 + 2][tid] = v[q].z;
            As[q * 4 + 3][tid] = v[q].w;
        }
        if (tid < 80) {
            int k = tid / 5, j = tid - k * 5;
            Bs[k][j] = Wr[((long)(kk * 16 + k)) * 5 + j];
        }
        __syncthreads();
        #pragma unroll
        for (int k = 0; k < 16; k++) {
            float a = As[k][tid];
            #pragma unroll
            for (int j = 0; j < 5; j++)
                acc[j] = fmaf(a, Bs[k][j], acc[j]);
        }
    }

    if (rv) {
        float s = scales[level];
        float gx = ((float)x + 0.5f) * strd;
        float gy = ((float)y + 0.5f) * strd;
        float r0 = expf((acc[0] + rb[0]) * s);
        float r1 = expf((acc[1] + rb[1]) * s);
        float r2 = expf((acc[2] + rb[2]) * s);
        float r3 = expf((acc[3] + rb[3]) * s);
        long row = (long)n * TOTPIX + pixbase + (y * Wd + x);
        float* o = out + row * OUTC;
        o[0] = gx - r0;
        o[1] = gy - r1;
        o[2] = gx + r2;
        o[3] = gy + r3;
        o[4] = acc[4] + ib[0];
    }
}

// ------------------------- host launcher -------------------------------------
extern "C" void kernel_launch(void* const* d_in, const int* in_sizes, int n_in,
                              void* d_out, int out_size) {
    (void)in_sizes; (void)n_in; (void)out_size;
    const float* pin[5] = {(const float*)d_in[0], (const float*)d_in[1],
                           (const float*)d_in[2], (const float*)d_in[3],
                           (const float*)d_in[4]};
    const float* cls_tw = (const float*)d_in[5];
    const float* cls_tb = (const float*)d_in[6];
    const float* cls_gn_g = (const float*)d_in[7];
    const float* cls_gn_b = (const float*)d_in[8];
    const float* reg_tw = (const float*)d_in[9];
    const float* reg_tb = (const float*)d_in[10];
    const float* reg_gn_g = (const float*)d_in[11];
    const float* reg_gn_b = (const float*)d_in[12];
    const float* cls_hw = (const float*)d_in[13];
    const float* cls_hb = (const float*)d_in[14];
    const float* reg_hw = (const float*)d_in[15];
    const float* reg_hb = (const float*)d_in[16];
    const float* iou_hw = (const float*)d_in[17];
    const float* iou_hb = (const float*)d_in[18];
    const float* scales = (const float*)d_in[19];
    float* out = (float*)d_out;

    float *P, *A, *B, *Wt, *Wc, *Wr, *Sc, *Sh;
    cudaGetSymbolAddress((void**)&P, g_P);
    cudaGetSymbolAddress((void**)&A, g_A);
    cudaGetSymbolAddress((void**)&B, g_B);
    cudaGetSymbolAddress((void**)&Wt, g_Wt);
    cudaGetSymbolAddress((void**)&Wc, g_Wc);
    cudaGetSymbolAddress((void**)&Wr, g_Wr);
    cudaGetSymbolAddress((void**)&Sc, g_scale);
    cudaGetSymbolAddress((void**)&Sh, g_shift);

    static const int HS[NLEV] = {100, 50, 25, 13, 7};
    static const int STRD[NLEV] = {8, 16, 32, 64, 128};
    static const int PIXB[NLEV] = {0, 10000, 12500, 13125, 13294};

    // weight transforms
    {
        int tot = 4 * KDIM * 256;
        k_wtower<<<(tot + 255) / 256, 256>>>(cls_tw, Wt, tot);
        k_wtower<<<(tot + 255) / 256, 256>>>(reg_tw, Wt + (long)4 * KDIM * 256, tot);
        k_wc<<<(KDIM * 80 + 255) / 256, 256>>>(cls_hw, Wc);
        k_wr<<<(KDIM * 5 + 255) / 256, 256>>>(reg_hw, iou_hw, Wr);
    }

    for (int lv = 0; lv < NLEV; lv++) {
        int H = HS[lv], Wd = HS[lv];
        int HW = H * Wd;
        int M = 2 * HW;

        dim3 tg((HW + 31) / 32, 8, 2);
        k_transpose<<<tg, dim3(32, 8)>>>(pin[lv], P, HW);

        for (int tower = 0; tower < 2; tower++) {
            const float* tb = tower ? reg_tb : cls_tb;
            const float* gg = tower ? reg_gn_g : cls_gn_g;
            const float* gb = tower ? reg_gn_b : cls_gn_b;
            const float* Wbase = Wt + (long)(tower ? 4 : 0) * KDIM * 256;
            const float* src = P;
            for (int l = 0; l < 4; l++) {
                dim3 g((M + BM - 1) / BM, 2);
                k_conv<<<g, 256>>>(src, Wbase + (long)l * KDIM * 256,
                                   tb + l * 256, B, H, Wd, HW, M);
                k_stats<<<64, 256>>>(B, gg + l * 256, gb + l * 256, Sc, Sh, HW);
                int tot4 = 2 * HW * 64;
                k_normrelu<<<(tot4 + 255) / 256, 256>>>(B, Sc, Sh, A, HW, tot4);
                src = A;
            }
            if (tower == 0) {
                k_clshead<<<(M + BM - 1) / BM, 256>>>(A, Wc, cls_hb,
                                                      H, Wd, HW, M, PIXB[lv], out);
            } else {
                k_reghead<<<(M + 255) / 256, 256>>>(A, Wr, reg_hb, iou_hb,
                                                    scales, lv, H, Wd, HW, M,
                                                    PIXB[lv], (float)STRD[lv], out);
            }
        }
    }
}

// round 2
// speedup vs baseline: 1.0491x; 1.0491x over previous
#include <cuda_runtime.h>
#include <math.h>

// ---------------------------------------------------------------------------
// FCOS head: 5 levels, batch 2, C=256.
// Strategy: NHWC implicit-GEMM fp32 convs on CUDA cores (baseline),
// GroupNorm folded into per-(n,c) scale/shift, fused norm+ReLU,
// heads as small-N GEMMs with decode epilogue.
// ---------------------------------------------------------------------------

#define NLEV 5
#define TOTPIX 13343
#define OUTC 85
#define KDIM 2304            // 9 * 256
#define MAXFEAT (2*100*100*256)

// ------------------------- device scratch (no runtime alloc) ----------------
__device__ __align__(128) float g_P[MAXFEAT];   // transposed NHWC input of level
__device__ __align__(128) float g_A[MAXFEAT];   // normalized activations
__device__ __align__(128) float g_B[MAXFEAT];   // raw conv output
__device__ __align__(128) float g_Wt[8 * KDIM * 256]; // 8 tower layers, [K,256]
__device__ __align__(128) float g_Wc[KDIM * 80];      // cls head [K,80]
__device__ __align__(128) float g_Wr[KDIM * 5];       // reg(4)+iou(1) head [K,5]
__device__ float g_scale[512];  // per (n, c) affine from GN
__device__ float g_shift[512];

// ------------------------- weight transforms --------------------------------
// tower: w[l][co][ci][ky][kx] -> wt[(l*K + (t*256+ci))*256 + co]
__global__ void k_wtower(const float* __restrict__ w, float* __restrict__ wt,
                         int total) {
    int idx = blockIdx.x * 256 + threadIdx.x;
    if (idx >= total) return;
    int co = idx & 255;
    int r = idx >> 8;              // l*KDIM + k
    int k = r % KDIM;
    int l = r / KDIM;
    int t = k >> 8;
    int ci = k & 255;
    wt[idx] = w[(((long)l * 256 + co) * 256 + ci) * 9 + t];
}

__global__ void k_wc(const float* __restrict__ w, float* __restrict__ wc) {
    int idx = blockIdx.x * 256 + threadIdx.x;
    if (idx >= KDIM * 80) return;
    int co = idx % 80;
    int k = idx / 80;
    int t = k >> 8;
    int ci = k & 255;
    wc[idx] = w[((co * 256 + ci) * 9) + t];
}

__global__ void k_wr(const float* __restrict__ wreg, const float* __restrict__ wiou,
                     float* __restrict__ wr) {
    int idx = blockIdx.x * 256 + threadIdx.x;
    if (idx >= KDIM * 5) return;
    int j = idx % 5;
    int k = idx / 5;
    int t = k >> 8;
    int ci = k & 255;
    wr[idx] = (j < 4) ? wreg[((j * 256 + ci) * 9) + t]
                      : wiou[(ci * 9) + t];
}

// ------------------------- NCHW -> NHWC transpose ----------------------------
// in: [2,256,HW]  out: [2,HW,256]
__global__ void k_transpose(const float* __restrict__ in, float* __restrict__ out,
                            int HW) {
    __shared__ float tile[32][33];
    int n = blockIdx.z;
    int c0 = blockIdx.y * 32;
    int s0 = blockIdx.x * 32;
    int tx = threadIdx.x, ty = threadIdx.y;
    #pragma unroll
    for (int i = ty; i < 32; i += 8) {
        int s = s0 + tx;
        tile[i][tx] = (s < HW) ? in[((long)n * 256 + c0 + i) * HW + s] : 0.f;
    }
    __syncthreads();
    #pragma unroll
    for (int i = ty; i < 32; i += 8) {
        int s = s0 + i;
        if (s < HW) out[((long)n * HW + s) * 256 + c0 + tx] = tile[tx][i];
    }
}

// ------------------------- conv implicit GEMM (BN=128) -----------------------
// X: NHWC [2,H,W,256].  Wt: [KDIM,256].  Y[m, co] = bias[co] + sum_k A[m,k]W[k,co]
// K ordered tap-major (tap = ky*3+kx), ci-minor.
#define BM 128
#define BK 16

__global__ __launch_bounds__(256) void k_conv(
    const float* __restrict__ X, const float* __restrict__ Wt,
    const float* __restrict__ bias, float* __restrict__ Y,
    int H, int Wd, int HW, int M) {
    __shared__ float As[BK][BM + 4];
    __shared__ float Bs[BK][128];

    int tid = threadIdx.x;
    int bm = blockIdx.x, bn = blockIdx.y;
    int tm = tid >> 4;          // 0..15, 8 rows each
    int tn = tid & 15;          // 0..15, 8 cols each

    // A loader: row = tid&127, half = tid>>7 (8 ci each)
    int ar = tid & 127;
    int ah = tid >> 7;
    int am = bm * BM + ar;
    int an = 0, ay = 0, ax = 0;
    bool arv = (am < M);
    if (arv) { an = am / HW; int p = am - an * HW; ay = p / Wd; ax = p - ay * Wd; }
    int abase = an * HW;
    int kc = ah * 8;

    // B loader
    int bk = tid >> 4;
    int bc = (tid & 15) * 8;

    float acc[8][8];
    #pragma unroll
    for (int i = 0; i < 8; i++)
        #pragma unroll
        for (int j = 0; j < 8; j++) acc[i][j] = 0.f;

    for (int kk = 0; kk < 144; kk++) {
        int tap = kk >> 4;
        int dy = tap / 3 - 1;
        int dx = tap - (tap / 3) * 3 - 1;
        int ci0 = (kk & 15) << 4;

        float4 v0 = make_float4(0.f, 0.f, 0.f, 0.f);
        float4 v1 = make_float4(0.f, 0.f, 0.f, 0.f);
        int yy = ay + dy, xx = ax + dx;
        if (arv && (unsigned)yy < (unsigned)H && (unsigned)xx < (unsigned)Wd) {
            const float4* src = (const float4*)(X + (((long)(abase + yy * Wd + xx)) << 8) + ci0 + kc);
            v0 = src[0]; v1 = src[1];
        }
        const float4* bsrc = (const float4*)(Wt + ((long)(kk * 16 + bk)) * 256 + (bn << 7) + bc);
        float4 w0 = bsrc[0], w1 = bsrc[1];

        __syncthreads();
        As[kc + 0][ar] = v0.x; As[kc + 1][ar] = v0.y;
        As[kc + 2][ar] = v0.z; As[kc + 3][ar] = v0.w;
        As[kc + 4][ar] = v1.x; As[kc + 5][ar] = v1.y;
        As[kc + 6][ar] = v1.z; As[kc + 7][ar] = v1.w;
        *(float4*)&Bs[bk][bc] = w0;
        *(float4*)&Bs[bk][bc + 4] = w1;
        __syncthreads();

        #pragma unroll
        for (int k = 0; k < BK; k++) {
            float4 a0 = *(const float4*)&As[k][tm * 8];
            float4 a1 = *(const float4*)&As[k][tm * 8 + 4];
            float4 b0 = *(const float4*)&Bs[k][tn * 8];
            float4 b1 = *(const float4*)&Bs[k][tn * 8 + 4];
            float a[8] = {a0.x, a0.y, a0.z, a0.w, a1.x, a1.y, a1.z, a1.w};
            float b[8] = {b0.x, b0.y, b0.z, b0.w, b1.x, b1.y, b1.z, b1.w};
            #pragma unroll
            for (int i = 0; i < 8; i++)
                #pragma unroll
                for (int j = 0; j < 8; j++)
                    acc[i][j] = fmaf(a[i], b[j], acc[i][j]);
        }
    }

    float bb[8];
    #pragma unroll
    for (int j = 0; j < 8; j++) bb[j] = bias[(bn << 7) + tn * 8 + j];
    #pragma unroll
    for (int i = 0; i < 8; i++) {
        int m = bm * BM + tm * 8 + i;
        if (m < M) {
            float4 o0, o1;
            o0.x = acc[i][0] + bb[0]; o0.y = acc[i][1] + bb[1];
            o0.z = acc[i][2] + bb[2]; o0.w = acc[i][3] + bb[3];
            o1.x = acc[i][4] + bb[4]; o1.y = acc[i][5] + bb[5];
            o1.z = acc[i][6] + bb[6]; o1.w = acc[i][7] + bb[7];
            float4* dst = (float4*)(Y + (((long)m) << 8) + (bn << 7) + tn * 8);
            dst[0] = o0; dst[1] = o1;
        }
    }
}

// ------------------------- GroupNorm stats -> per-(n,c) affine ---------------
__global__ void k_stats(const float* __restrict__ Y,
                        const float* __restrict__ gamma, const float* __restrict__ beta,
                        float* __restrict__ scale, float* __restrict__ shift, int HW) {
    int n = blockIdx.x >> 5;
    int g = blockIdx.x & 31;
    int tid = threadIdx.x;
    const float* base = Y + ((long)n * HW) * 256 + g * 8;
    float s = 0.f, ss = 0.f;
    for (int p = tid; p < HW; p += 256) {
        const float4* q = (const float4*)(base + ((long)p) * 256);
        float4 a = q[0], b = q[1];
        s += a.x + a.y + a.z + a.w + b.x + b.y + b.z + b.w;
        ss += a.x * a.x + a.y * a.y + a.z * a.z + a.w * a.w
            + b.x * b.x + b.y * b.y + b.z * b.z + b.w * b.w;
    }
    #pragma unroll
    for (int o = 16; o; o >>= 1) {
        s += __shfl_xor_sync(0xffffffffu, s, o);
        ss += __shfl_xor_sync(0xffffffffu, ss, o);
    }
    __shared__ float rs[8], rss[8];
    if ((tid & 31) == 0) { rs[tid >> 5] = s; rss[tid >> 5] = ss; }
    __syncthreads();
    if (tid == 0) {
        float S = 0.f, SS = 0.f;
        #pragma unroll
        for (int i = 0; i < 8; i++) { S += rs[i]; SS += rss[i]; }
        float cnt = (float)HW * 8.f;
        float mean = S / cnt;
        float var = SS / cnt - mean * mean;
        float rstd = rsqrtf(var + 1e-5f);
        #pragma unroll
        for (int c = 0; c < 8; c++) {
            int ch = g * 8 + c;
            float sc = rstd * gamma[ch];
            scale[n * 256 + ch] = sc;
            shift[n * 256 + ch] = beta[ch] - mean * sc;
        }
    }
}

// ------------------------- norm + ReLU ---------------------------------------
__global__ void k_normrelu(const float* __restrict__ Y,
                           const float* __restrict__ scale, const float* __restrict__ shift,
                           float* __restrict__ X, int HW, int total4) {
    int idx = blockIdx.x * 256 + threadIdx.x;
    if (idx >= total4) return;
    int per = HW * 64;
    int n = idx / per;
    int c = (idx & 63) * 4;
    float4 v = ((const float4*)Y)[idx];
    float4 sc = *(const float4*)(scale + n * 256 + c);
    float4 sf = *(const float4*)(shift + n * 256 + c);
    float4 o;
    o.x = fmaxf(fmaf(v.x, sc.x, sf.x), 0.f);
    o.y = fmaxf(fmaf(v.y, sc.y, sf.y), 0.f);
    o.z = fmaxf(fmaf(v.z, sc.z, sf.z), 0.f);
    o.w = fmaxf(fmaf(v.w, sc.w, sf.w), 0.f);
    ((float4*)X)[idx] = o;
}

// ------------------------- cls head (N=80) -----------------------------------
__global__ __launch_bounds__(256) void k_clshead(
    const float* __restrict__ X, const float* __restrict__ Wc,
    const float* __restrict__ hb,
    int H, int Wd, int HW, int M, int pixbase, float* __restrict__ out) {
    __shared__ float As[BK][BM + 4];
    __shared__ float Bs[BK][80];

    int tid = threadIdx.x;
    int bm = blockIdx.x;
    int tm = tid >> 4;          // 8 rows
    int tn = tid & 15;          // 5 cols

    int ar = tid & 127;
    int ah = tid >> 7;
    int am = bm * BM + ar;
    int an = 0, ay = 0, ax = 0;
    bool arv = (am < M);
    if (arv) { an = am / HW; int p = am - an * HW; ay = p / Wd; ax = p - ay * Wd; }
    int abase = an * HW;
    int kc = ah * 8;

    int lk = tid >> 4;          // B loader: k row
    int lc = (tid & 15) * 5;    // 5 cols each

    float acc[8][5];
    #pragma unroll
    for (int i = 0; i < 8; i++)
        #pragma unroll
        for (int j = 0; j < 5; j++) acc[i][j] = 0.f;

    for (int kk = 0; kk < 144; kk++) {
        int tap = kk >> 4;
        int dy = tap / 3 - 1;
        int dx = tap - (tap / 3) * 3 - 1;
        int ci0 = (kk & 15) << 4;

        float4 v0 = make_float4(0.f, 0.f, 0.f, 0.f);
        float4 v1 = make_float4(0.f, 0.f, 0.f, 0.f);
        int yy = ay + dy, xx = ax + dx;
        if (arv && (unsigned)yy < (unsigned)H && (unsigned)xx < (unsigned)Wd) {
            const float4* src = (const float4*)(X + (((long)(abase + yy * Wd + xx)) << 8) + ci0 + kc);
            v0 = src[0]; v1 = src[1];
        }
        float wv[5];
        #pragma unroll
        for (int j = 0; j < 5; j++)
            wv[j] = Wc[((long)(kk * 16 + lk)) * 80 + lc + j];

        __syncthreads();
        As[kc + 0][ar] = v0.x; As[kc + 1][ar] = v0.y;
        As[kc + 2][ar] = v0.z; As[kc + 3][ar] = v0.w;
        As[kc + 4][ar] = v1.x; As[kc + 5][ar] = v1.y;
        As[kc + 6][ar] = v1.z; As[kc + 7][ar] = v1.w;
        #pragma unroll
        for (int j = 0; j < 5; j++) Bs[lk][lc + j] = wv[j];
        __syncthreads();

        #pragma unroll
        for (int k = 0; k < BK; k++) {
            float4 a0 = *(const float4*)&As[k][tm * 8];
            float4 a1 = *(const float4*)&As[k][tm * 8 + 4];
            float a[8] = {a0.x, a0.y, a0.z, a0.w, a1.x, a1.y, a1.z, a1.w};
            float b[5];
            #pragma unroll
            for (int j = 0; j < 5; j++) b[j] = Bs[k][tn * 5 + j];
            #pragma unroll
            for (int i = 0; i < 8; i++)
                #pragma unroll
                for (int j = 0; j < 5; j++)
                    acc[i][j] = fmaf(a[i], b[j], acc[i][j]);
        }
    }

    float bb[5];
    #pragma unroll
    for (int j = 0; j < 5; j++) bb[j] = hb[tn * 5 + j];
    #pragma unroll
    for (int i = 0; i < 8; i++) {
        int m = bm * BM + tm * 8 + i;
        if (m < M) {
            int n = m / HW;
            int p = m - n * HW;
            long row = (long)n * TOTPIX + pixbase + p;
            float* o = out + row * OUTC + 5 + tn * 5;
            #pragma unroll
            for (int j = 0; j < 5; j++) o[j] = acc[i][j] + bb[j];
        }
    }
}

// ------------------------- reg+iou head (N=5) + decode -----------------------
__global__ __launch_bounds__(256) void k_reghead(
    const float* __restrict__ X, const float* __restrict__ Wr,
    const float* __restrict__ rb, const float* __restrict__ ib,
    const float* __restrict__ scales, int level,
    int H, int Wd, int HW, int M, int pixbase, float strd,
    float* __restrict__ out) {
    __shared__ float As[16][260];
    __shared__ float Bs[16][5];

    int tid = threadIdx.x;
    int m = blockIdx.x * 256 + tid;
    bool rv = (m < M);
    int n = 0, y = 0, x = 0;
    if (rv) { n = m / HW; int p = m - n * HW; y = p / Wd; x = p - y * Wd; }
    int abase = n * HW;

    float acc[5] = {0.f, 0.f, 0.f, 0.f, 0.f};

    for (int kk = 0; kk < 144; kk++) {
        int tap = kk >> 4;
        int dy = tap / 3 - 1;
        int dx = tap - (tap / 3) * 3 - 1;
        int ci0 = (kk & 15) << 4;

        float4 v[4];
        #pragma unroll
        for (int q = 0; q < 4; q++) v[q] = make_float4(0.f, 0.f, 0.f, 0.f);
        int yy = y + dy, xx = x + dx;
        if (rv && (unsigned)yy < (unsigned)H && (unsigned)xx < (unsigned)Wd) {
            const float4* src = (const float4*)(X + (((long)(abase + yy * Wd + xx)) << 8) + ci0);
            v[0] = src[0]; v[1] = src[1]; v[2] = src[2]; v[3] = src[3];
        }
        __syncthreads();
        #pragma unroll
        for (int q = 0; q < 4; q++) {
            As[q * 4 + 0][tid] = v[q].x;
            As[q * 4 + 1][tid] = v[q].y;
            As[q * 4 + 2][tid] = v[q].z;
            As[q * 4 + 3][tid] = v[q].w;
        }
        if (tid < 80) {
            int k = tid / 5, j = tid - k * 5;
            Bs[k][j] = Wr[((long)(kk * 16 + k)) * 5 + j];
        }
        __syncthreads();
        #pragma unroll
        for (int k = 0; k < 16; k++) {
            float a = As[k][tid];
            #pragma unroll
            for (int j = 0; j < 5; j++)
                acc[j] = fmaf(a, Bs[k][j], acc[j]);
        }
    }

    if (rv) {
        float s = scales[level];
        float gx = ((float)x + 0.5f) * strd;
        float gy = ((float)y + 0.5f) * strd;
        float r0 = expf((acc[0] + rb[0]) * s);
        float r1 = expf((acc[1] + rb[1]) * s);
        float r2 = expf((acc[2] + rb[2]) * s);
        float r3 = expf((acc[3] + rb[3]) * s);
        long row = (long)n * TOTPIX + pixbase + (y * Wd + x);
        float* o = out + row * OUTC;
        o[0] = gx - r0;
        o[1] = gy - r1;
        o[2] = gx + r2;
        o[3] = gy + r3;
        o[4] = acc[4] + ib[0];
    }
}

// ------------------------- host launcher -------------------------------------
extern "C" void kernel_launch(void* const* d_in, const int* in_sizes, int n_in,
                              void* d_out, int out_size) {
    (void)in_sizes; (void)n_in; (void)out_size;
    const float* pin[5] = {(const float*)d_in[0], (const float*)d_in[1],
                           (const float*)d_in[2], (const float*)d_in[3],
                           (const float*)d_in[4]};
    const float* cls_tw = (const float*)d_in[5];
    const float* cls_tb = (const float*)d_in[6];
    const float* cls_gn_g = (const float*)d_in[7];
    const float* cls_gn_b = (const float*)d_in[8];
    const float* reg_tw = (const float*)d_in[9];
    const float* reg_tb = (const float*)d_in[10];
    const float* reg_gn_g = (const float*)d_in[11];
    const float* reg_gn_b = (const float*)d_in[12];
    const float* cls_hw = (const float*)d_in[13];
    const float* cls_hb = (const float*)d_in[14];
    const float* reg_hw = (const float*)d_in[15];
    const float* reg_hb = (const float*)d_in[16];
    const float* iou_hw = (const float*)d_in[17];
    const float* iou_hb = (const float*)d_in[18];
    const float* scales = (const float*)d_in[19];
    float* out = (float*)d_out;

    float *P, *A, *B, *Wt, *Wc, *Wr, *Sc, *Sh;
    cudaGetSymbolAddress((void**)&P, g_P);
    cudaGetSymbolAddress((void**)&A, g_A);
    cudaGetSymbolAddress((void**)&B, g_B);
    cudaGetSymbolAddress((void**)&Wt, g_Wt);
    cudaGetSymbolAddress((void**)&Wc, g_Wc);
    cudaGetSymbolAddress((void**)&Wr, g_Wr);
    cudaGetSymbolAddress((void**)&Sc, g_scale);
    cudaGetSymbolAddress((void**)&Sh, g_shift);

    static const int HS[NLEV] = {100, 50, 25, 13, 7};
    static const int STRD[NLEV] = {8, 16, 32, 64, 128};
    static const int PIXB[NLEV] = {0, 10000, 12500, 13125, 13294};

    // weight transforms
    {
        int tot = 4 * KDIM * 256;
        k_wtower<<<(tot + 255) / 256, 256>>>(cls_tw, Wt, tot);
        k_wtower<<<(tot + 255) / 256, 256>>>(reg_tw, Wt + (long)4 * KDIM * 256, tot);
        k_wc<<<(KDIM * 80 + 255) / 256, 256>>>(cls_hw, Wc);
        k_wr<<<(KDIM * 5 + 255) / 256, 256>>>(reg_hw, iou_hw, Wr);
    }

    for (int lv = 0; lv < NLEV; lv++) {
        int H = HS[lv], Wd = HS[lv];
        int HW = H * Wd;
        int M = 2 * HW;

        dim3 tg((HW + 31) / 32, 8, 2);
        k_transpose<<<tg, dim3(32, 8)>>>(pin[lv], P, HW);

        for (int tower = 0; tower < 2; tower++) {
            const float* tb = tower ? reg_tb : cls_tb;
            const float* gg = tower ? reg_gn_g : cls_gn_g;
            const float* gb = tower ? reg_gn_b : cls_gn_b;
            const float* Wbase = Wt + (long)(tower ? 4 : 0) * KDIM * 256;
            const float* src = P;
            for (int l = 0; l < 4; l++) {
                dim3 g((M + BM - 1) / BM, 2);
                k_conv<<<g, 256>>>(src, Wbase + (long)l * KDIM * 256,
                                   tb + l * 256, B, H, Wd, HW, M);
                k_stats<<<64, 256>>>(B, gg + l * 256, gb + l * 256, Sc, Sh, HW);
                int tot4 = 2 * HW * 64;
                k_normrelu<<<(tot4 + 255) / 256, 256>>>(B, Sc, Sh, A, HW, tot4);
                src = A;
            }
            if (tower == 0) {
                k_clshead<<<(M + BM - 1) / BM, 256>>>(A, Wc, cls_hb,
                                                      H, Wd, HW, M, PIXB[lv], out);
            } else {
                k_reghead<<<(M + 255) / 256, 256>>>(A, Wr, reg_hb, iou_hb,
                                                    scales, lv, H, Wd, HW, M,
                                                    PIXB[lv], (float)STRD[lv], out);
            }
        }
    }
}

// round 4
// speedup vs baseline: 3.5683x; 3.4012x over previous
#include <cuda_runtime.h>
#include <cuda_bf16.h>
#include <stdint.h>
#include <math.h>

// ---------------------------------------------------------------------------
// FCOS head — mma.sync bf16 hi/lo split implicit-GEMM towers, batched levels.
// (tcgen05 unavailable: harness PTX target is plain sm_100)
// ---------------------------------------------------------------------------

#define TOTPIX 13343
#define PIX2   26686
#define KDIM   2304
#define OUTC   85

__constant__ int c_HW[5]   = {10000, 2500, 625, 169, 49};
__constant__ int c_Wl[5]   = {100, 50, 25, 13, 7};
__constant__ int c_B2[6]   = {0, 20000, 25000, 26250, 26588, 26686};
__constant__ int c_TILB[6] = {0, 157, 197, 207, 210, 211};

// ------------------------- device scratch ------------------------------------
__device__ __align__(128) __nv_bfloat16 g_Xp_hi[PIX2 * 256];
__device__ __align__(128) __nv_bfloat16 g_Xp_lo[PIX2 * 256];
__device__ __align__(128) __nv_bfloat16 g_Xhi0[PIX2 * 256];
__device__ __align__(128) __nv_bfloat16 g_Xlo0[PIX2 * 256];
__device__ __align__(128) __nv_bfloat16 g_Xhi1[PIX2 * 256];
__device__ __align__(128) __nv_bfloat16 g_Xlo1[PIX2 * 256];
__device__ __align__(128) float g_Y[2 * PIX2 * 256];
__device__ __align__(128) __nv_bfloat16 g_Whi[8 * 256 * KDIM];
__device__ __align__(128) __nv_bfloat16 g_Wlo[8 * 256 * KDIM];
__device__ __align__(128) float g_Wc[KDIM * 80];
__device__ __align__(128) float g_Wr[KDIM * 5];
__device__ float g_scale[2 * 5 * 2 * 256];
__device__ float g_shift[2 * 5 * 2 * 256];

// ------------------------- helpers -------------------------------------------
__device__ __forceinline__ uint32_t smem_u32(const void* p) {
    uint32_t a;
    asm("{ .reg .u64 t; cvta.to.shared.u64 t, %1; cvt.u32.u64 %0, t; }"
        : "=r"(a) : "l"(p));
    return a;
}

#define LDSM4(r, addr) \
    asm volatile("ldmatrix.sync.aligned.m8n8.x4.shared.b16 {%0,%1,%2,%3}, [%4];" \
                 : "=r"((r)[0]), "=r"((r)[1]), "=r"((r)[2]), "=r"((r)[3]) \
                 : "r"(addr))

__device__ __forceinline__ void mma_bf16(float* c, const uint32_t* a,
                                         uint32_t b0, uint32_t b1) {
    asm volatile(
        "mma.sync.aligned.m16n8k16.row.col.f32.bf16.bf16.f32 "
        "{%0,%1,%2,%3}, {%4,%5,%6,%7}, {%8,%9}, {%0,%1,%2,%3};"
        : "+f"(c[0]), "+f"(c[1]), "+f"(c[2]), "+f"(c[3])
        : "r"(a[0]), "r"(a[1]), "r"(a[2]), "r"(a[3]), "r"(b0), "r"(b1));
}

// hi/lo -> 8 floats
__device__ __forceinline__ void bf8(const uint4 uh, const uint4 ul, float* f) {
    const __nv_bfloat162* a = (const __nv_bfloat162*)&uh;
    const __nv_bfloat162* b = (const __nv_bfloat162*)&ul;
#pragma unroll
    for (int i = 0; i < 4; i++) {
        float2 x = __bfloat1622float2(a[i]);
        float2 y = __bfloat1622float2(b[i]);
        f[2 * i] = x.x + y.x;
        f[2 * i + 1] = x.y + y.y;
    }
}

// ------------------------- weight transforms ---------------------------------
__global__ void k_wsplit(const float* __restrict__ cls_tw,
                         const float* __restrict__ reg_tw,
                         __nv_bfloat16* __restrict__ Whi,
                         __nv_bfloat16* __restrict__ Wlo) {
    int idx = blockIdx.x * 256 + threadIdx.x;
    if (idx >= 8 * 256 * KDIM) return;
    int k = idx % KDIM;
    int co = (idx / KDIM) & 255;
    int l8 = idx / (KDIM * 256);
    int tower = l8 >> 2, l = l8 & 3;
    int tap = k >> 8, ci = k & 255;
    const float* w = tower ? reg_tw : cls_tw;
    float v = w[(((size_t)l * 256 + co) * 256 + ci) * 9 + tap];
    __nv_bfloat16 h = __float2bfloat16(v);
    Whi[idx] = h;
    Wlo[idx] = __float2bfloat16(v - __bfloat162float(h));
}

__global__ void k_wc(const float* __restrict__ w, float* __restrict__ wc) {
    int idx = blockIdx.x * 256 + threadIdx.x;
    if (idx >= KDIM * 80) return;
    int co = idx % 80;
    int k = idx / 80;
    int t = k >> 8, ci = k & 255;
    wc[idx] = w[((co * 256 + ci) * 9) + t];
}

__global__ void k_wr(const float* __restrict__ wreg, const float* __restrict__ wiou,
                     float* __restrict__ wr) {
    int idx = blockIdx.x * 256 + threadIdx.x;
    if (idx >= KDIM * 5) return;
    int j = idx % 5;
    int k = idx / 5;
    int t = k >> 8, ci = k & 255;
    wr[idx] = (j < 4) ? wreg[((j * 256 + ci) * 9) + t] : wiou[(ci * 9) + t];
}

// ------------------------- input prep: NCHW fp32 -> NHWC hi/lo bf16 ----------
__global__ void k_prep(const float* __restrict__ in, __nv_bfloat16* __restrict__ hi,
                       __nv_bfloat16* __restrict__ lo, int HW, int base2) {
    __shared__ float tile[32][33];
    int n = blockIdx.z;
    int c0 = blockIdx.y * 32;
    int s0 = blockIdx.x * 32;
    int tx = threadIdx.x, ty = threadIdx.y;
#pragma unroll
    for (int i = ty; i < 32; i += 8) {
        int s = s0 + tx;
        tile[i][tx] = (s < HW) ? in[((size_t)n * 256 + c0 + i) * HW + s] : 0.f;
    }
    __syncthreads();
#pragma unroll
    for (int i = ty; i < 32; i += 8) {
        int s = s0 + i;
        if (s < HW) {
            float v = tile[tx][i];
            size_t o = ((size_t)(base2 + n * HW + s)) * 256 + c0 + tx;
            __nv_bfloat16 h = __float2bfloat16(v);
            hi[o] = h;
            lo[o] = __float2bfloat16(v - __bfloat162float(h));
        }
    }
}

// ------------------------- conv via mma.sync ---------------------------------
// smem: 4 tiles of 128 rows x 16 bf16, row stride 48B (conflict-free ldmatrix)
#define T_AH 0
#define T_AL 6144
#define T_BH 12288
#define T_BL 18432

__global__ __launch_bounds__(256) void k_conv_mma(
    const __nv_bfloat16* __restrict__ X0h, const __nv_bfloat16* __restrict__ X0l,
    const __nv_bfloat16* __restrict__ X1h, const __nv_bfloat16* __restrict__ X1l,
    const float* __restrict__ cls_tb, const float* __restrict__ reg_tb,
    float* __restrict__ Y, int layer) {
    __shared__ __align__(16) char smem[24576];
    uint32_t sb = smem_u32(smem);

    int tid = threadIdx.x;
    int wid = tid >> 5, lane = tid & 31;
    int mt = blockIdx.x;
    int tower = blockIdx.y;
    int coh = blockIdx.z;

    int lv = 0;
    while (lv < 4 && mt >= c_TILB[lv + 1]) lv++;
    int HW = c_HW[lv], Wd = c_Wl[lv];
    int M = 2 * HW;
    int m0 = (mt - c_TILB[lv]) * 128;
    int base2 = c_B2[lv];

    const __nv_bfloat16* Xh = tower ? X1h : X0h;
    const __nv_bfloat16* Xl = tower ? X1l : X0l;
    size_t wbase = ((size_t)((tower * 4 + layer) * 256 + coh * 128)) * KDIM;

    // ---- loader state: each thread loads 8 bf16 per tile per chunk ----------
    int lr = tid >> 1;       // row 0..127
    int lh = tid & 1;        // which 8-ci half
    int m = m0 + lr;
    bool av = (m < M);
    int n = 0, y = 0, x = 0;
    if (av) { n = m / HW; int p = m - n * HW; y = p / Wd; x = p - y * Wd; }
    int ptap[9];
#pragma unroll
    for (int t = 0; t < 9; t++) {
        int dy = t / 3 - 1, dx = t % 3 - 1;
        int yy = y + dy, xx = x + dx;
        ptap[t] = (av && (unsigned)yy < (unsigned)Wd && (unsigned)xx < (unsigned)Wd)
                      ? (base2 + n * HW + yy * Wd + xx) : -1;
    }
    const __nv_bfloat16* Whp = g_Whi + wbase + (size_t)lr * KDIM + lh * 8;
    const __nv_bfloat16* Wlp = g_Wlo + wbase + (size_t)lr * KDIM + lh * 8;
    uint32_t st_off = (uint32_t)(lr * 48 + lh * 16);

    // ---- ldmatrix addresses -------------------------------------------------
    int warp_m = wid & 3;     // 4 -> 32 rows each
    int warp_n = wid >> 2;    // 2 -> 64 cols each
    uint32_t lm = lane & 15, l16 = lane >> 4;
    uint32_t aoff0 = (warp_m * 32 + lm) * 48 + l16 * 16;
    uint32_t aoff1 = aoff0 + 16 * 48;
    uint32_t boff[4];
#pragma unroll
    for (int j = 0; j < 4; j++)
        boff[j] = (warp_n * 64 + j * 16 + lm) * 48 + l16 * 16;

    float acc[2][8][4];
#pragma unroll
    for (int i = 0; i < 2; i++)
#pragma unroll
        for (int j = 0; j < 8; j++)
#pragma unroll
            for (int q = 0; q < 4; q++) acc[i][j][q] = 0.f;

    uint4 pa_h, pa_l, pb_h, pb_l;
    {   // prefetch chunk 0
        int ci = lh * 8;
        int p = ptap[0];
        if (p >= 0) {
            size_t o = (((size_t)p) << 8) + ci;
            pa_h = *(const uint4*)(Xh + o);
            pa_l = *(const uint4*)(Xl + o);
        } else {
            pa_h = make_uint4(0, 0, 0, 0); pa_l = pa_h;
        }
        pb_h = *(const uint4*)(Whp);
        pb_l = *(const uint4*)(Wlp);
    }

    for (int kk = 0; kk < 144; kk++) {
        __syncthreads();
        *(uint4*)(smem + T_AH + st_off) = pa_h;
        *(uint4*)(smem + T_AL + st_off) = pa_l;
        *(uint4*)(smem + T_BH + st_off) = pb_h;
        *(uint4*)(smem + T_BL + st_off) = pb_l;
        __syncthreads();

        if (kk < 143) {   // prefetch next chunk
            int k2 = kk + 1;
            int tap = k2 >> 4;
            int ci = ((k2 & 15) << 4) + lh * 8;
            int p = ptap[tap];
            if (p >= 0) {
                size_t o = (((size_t)p) << 8) + ci;
                pa_h = *(const uint4*)(Xh + o);
                pa_l = *(const uint4*)(Xl + o);
            } else {
                pa_h = make_uint4(0, 0, 0, 0); pa_l = pa_h;
            }
            pb_h = *(const uint4*)(Whp + (size_t)k2 * 16);
            pb_l = *(const uint4*)(Wlp + (size_t)k2 * 16);
        }

        uint32_t Ah[2][4], Al[2][4], Bh[4][4], Bl[4][4];
        LDSM4(Ah[0], sb + T_AH + aoff0);
        LDSM4(Ah[1], sb + T_AH + aoff1);
        LDSM4(Al[0], sb + T_AL + aoff0);
        LDSM4(Al[1], sb + T_AL + aoff1);
#pragma unroll
        for (int j = 0; j < 4; j++) {
            LDSM4(Bh[j], sb + T_BH + boff[j]);
            LDSM4(Bl[j], sb + T_BL + boff[j]);
        }

#pragma unroll
        for (int i = 0; i < 2; i++) {
#pragma unroll
            for (int j = 0; j < 4; j++) {
                // n-tile 2j: frags {r0, r2};  n-tile 2j+1: {r1, r3}
                mma_bf16(acc[i][2 * j],     Ah[i], Bh[j][0], Bh[j][2]);
                mma_bf16(acc[i][2 * j],     Ah[i], Bl[j][0], Bl[j][2]);
                mma_bf16(acc[i][2 * j],     Al[i], Bh[j][0], Bh[j][2]);
                mma_bf16(acc[i][2 * j + 1], Ah[i], Bh[j][1], Bh[j][3]);
                mma_bf16(acc[i][2 * j + 1], Ah[i], Bl[j][1], Bl[j][3]);
                mma_bf16(acc[i][2 * j + 1], Al[i], Bh[j][1], Bh[j][3]);
            }
        }
    }

    // ---- epilogue: bias + store fp32 ---------------------------------------
    const float* bias = (tower ? reg_tb : cls_tb) + layer * 256;
    int r4 = lane >> 2, c2 = (lane & 3) * 2;
#pragma unroll
    for (int i = 0; i < 2; i++) {
#pragma unroll
        for (int j = 0; j < 8; j++) {
            int col = coh * 128 + warp_n * 64 + j * 8 + c2;
            float b0 = bias[col], b1 = bias[col + 1];
            int mr0 = m0 + warp_m * 32 + i * 16 + r4;
            if (mr0 < M) {
                float* o = Y + ((size_t)(tower * PIX2 + base2 + mr0)) * 256 + col;
                o[0] = acc[i][j][0] + b0;
                o[1] = acc[i][j][1] + b1;
            }
            int mr1 = mr0 + 8;
            if (mr1 < M) {
                float* o = Y + ((size_t)(tower * PIX2 + base2 + mr1)) * 256 + col;
                o[0] = acc[i][j][2] + b0;
                o[1] = acc[i][j][3] + b1;
            }
        }
    }
}

// ------------------------- GN stats ------------------------------------------
__global__ void k_stats(const float* __restrict__ Y,
                        const float* __restrict__ gc, const float* __restrict__ bc,
                        const float* __restrict__ gr, const float* __restrict__ br,
                        float* __restrict__ scale, float* __restrict__ shift) {
    int bid = blockIdx.x;
    int tower = bid / 320;
    int rr = bid - tower * 320;
    int lv = rr >> 6;
    int r2 = rr & 63;
    int n = r2 >> 5;
    int g = r2 & 31;
    int HW = c_HW[lv];
    int tid = threadIdx.x;
    const float* base = Y + ((size_t)(tower * PIX2 + c_B2[lv] + n * HW)) * 256 + g * 8;
    float s = 0.f, ss = 0.f;
    for (int p = tid; p < HW; p += 256) {
        const float4* q = (const float4*)(base + ((size_t)p) * 256);
        float4 a = q[0], b = q[1];
        s += a.x + a.y + a.z + a.w + b.x + b.y + b.z + b.w;
        ss += a.x * a.x + a.y * a.y + a.z * a.z + a.w * a.w
            + b.x * b.x + b.y * b.y + b.z * b.z + b.w * b.w;
    }
#pragma unroll
    for (int o = 16; o; o >>= 1) {
        s += __shfl_xor_sync(0xffffffffu, s, o);
        ss += __shfl_xor_sync(0xffffffffu, ss, o);
    }
    __shared__ float rs[8], rss[8];
    if ((tid & 31) == 0) { rs[tid >> 5] = s; rss[tid >> 5] = ss; }
    __syncthreads();
    if (tid == 0) {
        float S = 0.f, SS = 0.f;
#pragma unroll
        for (int i = 0; i < 8; i++) { S += rs[i]; SS += rss[i]; }
        float cnt = (float)HW * 8.f;
        float mean = S / cnt;
        float var = SS / cnt - mean * mean;
        float rstd = rsqrtf(var + 1e-5f);
        const float* gamma = tower ? gr : gc;
        const float* beta = tower ? br : bc;
        int oi = ((tower * 5 + lv) * 2 + n) * 256;
#pragma unroll
        for (int c = 0; c < 8; c++) {
            int ch = g * 8 + c;
            float sc = rstd * gamma[ch];
            scale[oi + ch] = sc;
            shift[oi + ch] = beta[ch] - mean * sc;
        }
    }
}

// ------------------------- norm + ReLU -> hi/lo bf16 -------------------------
__global__ void k_nr(const float* __restrict__ Y,
                     const float* __restrict__ scale, const float* __restrict__ shift,
                     __nv_bfloat16* __restrict__ X0h, __nv_bfloat16* __restrict__ X0l,
                     __nv_bfloat16* __restrict__ X1h, __nv_bfloat16* __restrict__ X1l) {
    int idx = blockIdx.x * 256 + threadIdx.x;
    if (idx >= 2 * PIX2 * 64) return;
    int tower = idx / (PIX2 * 64);
    int r = idx - tower * (PIX2 * 64);
    int pix = r >> 6;
    int c = (r & 63) << 2;
    int lv = 0;
    while (lv < 4 && pix >= c_B2[lv + 1]) lv++;
    int n = (pix - c_B2[lv]) / c_HW[lv];
    int si = ((tower * 5 + lv) * 2 + n) * 256 + c;
    float4 v = ((const float4*)Y)[idx];
    float4 s4 = *(const float4*)(scale + si);
    float4 h4 = *(const float4*)(shift + si);
    float o0 = fmaxf(fmaf(v.x, s4.x, h4.x), 0.f);
    float o1 = fmaxf(fmaf(v.y, s4.y, h4.y), 0.f);
    float o2 = fmaxf(fmaf(v.z, s4.z, h4.z), 0.f);
    float o3 = fmaxf(fmaf(v.w, s4.w, h4.w), 0.f);
    __nv_bfloat16* Hh = tower ? X1h : X0h;
    __nv_bfloat16* Hl = tower ? X1l : X0l;
    size_t off = (((size_t)pix) << 8) + c;
    __nv_bfloat16 b0 = __float2bfloat16(o0), b1 = __float2bfloat16(o1);
    __nv_bfloat16 b2 = __float2bfloat16(o2), b3 = __float2bfloat16(o3);
    *(__nv_bfloat162*)(Hh + off) = __nv_bfloat162(b0, b1);
    *(__nv_bfloat162*)(Hh + off + 2) = __nv_bfloat162(b2, b3);
    *(__nv_bfloat162*)(Hl + off) = __nv_bfloat162(
        __float2bfloat16(o0 - __bfloat162float(b0)),
        __float2bfloat16(o1 - __bfloat162float(b1)));
    *(__nv_bfloat162*)(Hl + off + 2) = __nv_bfloat162(
        __float2bfloat16(o2 - __bfloat162float(b2)),
        __float2bfloat16(o3 - __bfloat162float(b3)));
}

// ------------------------- cls head (N=80, fp32) -----------------------------
#define BM 128
#define BK 16

__global__ __launch_bounds__(256) void k_clshead(
    const __nv_bfloat16* __restrict__ Xh, const __nv_bfloat16* __restrict__ Xl,
    const float* __restrict__ Wc, const float* __restrict__ hb,
    int H, int Wd, int HW, int M, int pixbase, float* __restrict__ out) {
    __shared__ float As[BK][BM + 4];
    __shared__ float Bs[BK][80];

    int tid = threadIdx.x;
    int bm = blockIdx.x;
    int tm = tid >> 4;
    int tn = tid & 15;

    int ar = tid & 127;
    int ah = tid >> 7;
    int am = bm * BM + ar;
    int an = 0, ay = 0, ax = 0;
    bool arv = (am < M);
    if (arv) { an = am / HW; int p = am - an * HW; ay = p / Wd; ax = p - ay * Wd; }
    int abase = an * HW;
    int kc = ah * 8;

    int lk = tid >> 4;
    int lc = (tid & 15) * 5;

    float acc[8][5];
#pragma unroll
    for (int i = 0; i < 8; i++)
#pragma unroll
        for (int j = 0; j < 5; j++) acc[i][j] = 0.f;

    for (int kk = 0; kk < 144; kk++) {
        int tap = kk >> 4;
        int dy = tap / 3 - 1;
        int dx = tap - (tap / 3) * 3 - 1;
        int ci0 = (kk & 15) << 4;

        float f[8] = {0, 0, 0, 0, 0, 0, 0, 0};
        int yy = ay + dy, xx = ax + dx;
        if (arv && (unsigned)yy < (unsigned)H && (unsigned)xx < (unsigned)Wd) {
            size_t pe = ((size_t)(abase + yy * Wd + xx)) << 8;
            uint4 uh = *(const uint4*)(Xh + pe + ci0 + kc);
            uint4 ul = *(const uint4*)(Xl + pe + ci0 + kc);
            bf8(uh, ul, f);
        }
        float wv[5];
#pragma unroll
        for (int j = 0; j < 5; j++)
            wv[j] = Wc[((size_t)(kk * 16 + lk)) * 80 + lc + j];

        __syncthreads();
#pragma unroll
        for (int i = 0; i < 8; i++) As[kc + i][ar] = f[i];
#pragma unroll
        for (int j = 0; j < 5; j++) Bs[lk][lc + j] = wv[j];
        __syncthreads();

#pragma unroll
        for (int k = 0; k < BK; k++) {
            float4 a0 = *(const float4*)&As[k][tm * 8];
            float4 a1 = *(const float4*)&As[k][tm * 8 + 4];
            float a[8] = {a0.x, a0.y, a0.z, a0.w, a1.x, a1.y, a1.z, a1.w};
            float b[5];
#pragma unroll
            for (int j = 0; j < 5; j++) b[j] = Bs[k][tn * 5 + j];
#pragma unroll
            for (int i = 0; i < 8; i++)
#pragma unroll
                for (int j = 0; j < 5; j++)
                    acc[i][j] = fmaf(a[i], b[j], acc[i][j]);
        }
    }

    float bb[5];
#pragma unroll
    for (int j = 0; j < 5; j++) bb[j] = hb[tn * 5 + j];
#pragma unroll
    for (int i = 0; i < 8; i++) {
        int m = bm * BM + tm * 8 + i;
        if (m < M) {
            int n = m / HW;
            int p = m - n * HW;
            size_t row = (size_t)n * TOTPIX + pixbase + p;
            float* o = out + row * OUTC + 5 + tn * 5;
#pragma unroll
            for (int j = 0; j < 5; j++) o[j] = acc[i][j] + bb[j];
        }
    }
}

// ------------------------- reg+iou head + decode -----------------------------
__global__ __launch_bounds__(256) void k_reghead(
    const __nv_bfloat16* __restrict__ Xh, const __nv_bfloat16* __restrict__ Xl,
    const float* __restrict__ Wr,
    const float* __restrict__ rb, const float* __restrict__ ib,
    const float* __restrict__ scales, int level,
    int H, int Wd, int HW, int M, int pixbase, float strd,
    float* __restrict__ out) {
    __shared__ float As[16][260];
    __shared__ float Bs[16][5];

    int tid = threadIdx.x;
    int m = blockIdx.x * 256 + tid;
    bool rv = (m < M);
    int n = 0, y = 0, x = 0;
    if (rv) { n = m / HW; int p = m - n * HW; y = p / Wd; x = p - y * Wd; }
    int abase = n * HW;

    float acc[5] = {0.f, 0.f, 0.f, 0.f, 0.f};

    for (int kk = 0; kk < 144; kk++) {
        int tap = kk >> 4;
        int dy = tap / 3 - 1;
        int dx = tap - (tap / 3) * 3 - 1;
        int ci0 = (kk & 15) << 4;

        float f[16];
#pragma unroll
        for (int q = 0; q < 16; q++) f[q] = 0.f;
        int yy = y + dy, xx = x + dx;
        if (rv && (unsigned)yy < (unsigned)H && (unsigned)xx < (unsigned)Wd) {
            size_t pe = ((size_t)(abase + yy * Wd + xx)) << 8;
            const uint4* ph = (const uint4*)(Xh + pe + ci0);
            const uint4* pl = (const uint4*)(Xl + pe + ci0);
            bf8(ph[0], pl[0], f);
            bf8(ph[1], pl[1], f + 8);
        }
        __syncthreads();
#pragma unroll
        for (int q = 0; q < 16; q++) As[q][tid] = f[q];
        if (tid < 80) {
            int k = tid / 5, j = tid - k * 5;
            Bs[k][j] = Wr[((size_t)(kk * 16 + k)) * 5 + j];
        }
        __syncthreads();
#pragma unroll
        for (int k = 0; k < 16; k++) {
            float a = As[k][tid];
#pragma unroll
            for (int j = 0; j < 5; j++)
                acc[j] = fmaf(a, Bs[k][j], acc[j]);
        }
    }

    if (rv) {
        float s = scales[level];
        float gx = ((float)x + 0.5f) * strd;
        float gy = ((float)y + 0.5f) * strd;
        float r0 = expf((acc[0] + rb[0]) * s);
        float r1 = expf((acc[1] + rb[1]) * s);
        float r2 = expf((acc[2] + rb[2]) * s);
        float r3 = expf((acc[3] + rb[3]) * s);
        size_t row = (size_t)n * TOTPIX + pixbase + (y * Wd + x);
        float* o = out + row * OUTC;
        o[0] = gx - r0;
        o[1] = gy - r1;
        o[2] = gx + r2;
        o[3] = gy + r3;
        o[4] = acc[4] + ib[0];
    }
}

// ------------------------- host launcher -------------------------------------
extern "C" void kernel_launch(void* const* d_in, const int* in_sizes, int n_in,
                              void* d_out, int out_size) {
    (void)in_sizes; (void)n_in; (void)out_size;
    const float* pin[5] = {(const float*)d_in[0], (const float*)d_in[1],
                           (const float*)d_in[2], (const float*)d_in[3],
                           (const float*)d_in[4]};
    const float* cls_tw = (const float*)d_in[5];
    const float* cls_tb = (const float*)d_in[6];
    const float* cls_gn_g = (const float*)d_in[7];
    const float* cls_gn_b = (const float*)d_in[8];
    const float* reg_tw = (const float*)d_in[9];
    const float* reg_tb = (const float*)d_in[10];
    const float* reg_gn_g = (const float*)d_in[11];
    const float* reg_gn_b = (const float*)d_in[12];
    const float* cls_hw = (const float*)d_in[13];
    const float* cls_hb = (const float*)d_in[14];
    const float* reg_hw = (const float*)d_in[15];
    const float* reg_hb = (const float*)d_in[16];
    const float* iou_hw = (const float*)d_in[17];
    const float* iou_hb = (const float*)d_in[18];
    const float* scales = (const float*)d_in[19];
    float* out = (float*)d_out;

    __nv_bfloat16 *Xph, *Xpl, *X0h, *X0l, *X1h, *X1l, *Whi, *Wlo;
    float *Y, *Wc, *Wr, *Sc, *Sh;
    cudaGetSymbolAddress((void**)&Xph, g_Xp_hi);
    cudaGetSymbolAddress((void**)&Xpl, g_Xp_lo);
    cudaGetSymbolAddress((void**)&X0h, g_Xhi0);
    cudaGetSymbolAddress((void**)&X0l, g_Xlo0);
    cudaGetSymbolAddress((void**)&X1h, g_Xhi1);
    cudaGetSymbolAddress((void**)&X1l, g_Xlo1);
    cudaGetSymbolAddress((void**)&Whi, g_Whi);
    cudaGetSymbolAddress((void**)&Wlo, g_Wlo);
    cudaGetSymbolAddress((void**)&Y, g_Y);
    cudaGetSymbolAddress((void**)&Wc, g_Wc);
    cudaGetSymbolAddress((void**)&Wr, g_Wr);
    cudaGetSymbolAddress((void**)&Sc, g_scale);
    cudaGetSymbolAddress((void**)&Sh, g_shift);

    static const int HS[5] = {100, 50, 25, 13, 7};
    static const int STRD[5] = {8, 16, 32, 64, 128};
    static const int PIXB[5] = {0, 10000, 12500, 13125, 13294};
    static const int B2H[5] = {0, 20000, 25000, 26250, 26588};

    // weights
    {
        int tot = 8 * 256 * KDIM;
        k_wsplit<<<(tot + 255) / 256, 256>>>(cls_tw, reg_tw, Whi, Wlo);
        k_wc<<<(KDIM * 80 + 255) / 256, 256>>>(cls_hw, Wc);
        k_wr<<<(KDIM * 5 + 255) / 256, 256>>>(reg_hw, iou_hw, Wr);
    }

    // input prep
    for (int lv = 0; lv < 5; lv++) {
        int HW = HS[lv] * HS[lv];
        dim3 g((HW + 31) / 32, 8, 2);
        k_prep<<<g, dim3(32, 8)>>>(pin[lv], Xph, Xpl, HW, B2H[lv]);
    }

    // towers: 4 layers, batched over levels+towers+co-halves
    for (int l = 0; l < 4; l++) {
        const __nv_bfloat16* ah = (l == 0) ? Xph : X0h;
        const __nv_bfloat16* al = (l == 0) ? Xpl : X0l;
        const __nv_bfloat16* bh = (l == 0) ? Xph : X1h;
        const __nv_bfloat16* bl = (l == 0) ? Xpl : X1l;
        k_conv_mma<<<dim3(211, 2, 2), 256>>>(ah, al, bh, bl, cls_tb, reg_tb, Y, l);
        k_stats<<<640, 256>>>(Y, cls_gn_g + l * 256, cls_gn_b + l * 256,
                              reg_gn_g + l * 256, reg_gn_b + l * 256, Sc, Sh);
        k_nr<<<(2 * PIX2 * 64 + 255) / 256, 256>>>(Y, Sc, Sh, X0h, X0l, X1h, X1l);
    }

    // heads
    for (int lv = 0; lv < 5; lv++) {
        int H = HS[lv], Wd = HS[lv];
        int HW = H * Wd;
        int M = 2 * HW;
        size_t off = ((size_t)B2H[lv]) * 256;
        k_clshead<<<(M + BM - 1) / BM, 256>>>(X0h + off, X0l + off, Wc, cls_hb,
                                              H, Wd, HW, M, PIXB[lv], out);
        k_reghead<<<(M + 255) / 256, 256>>>(X1h + off, X1l + off, Wr, reg_hb,
                                            iou_hb, scales, lv, H, Wd, HW, M,
                                            PIXB[lv], (float)STRD[lv], out);
    }
}